// round 5
// baseline (speedup 1.0000x reference)
#include <cuda_runtime.h>

// Dempster-Shafer combine, algebraically reduced.
//
// Reference (per pixel, per class c):
//   b = (alpha-1)/S, u = C/S, K = sum_outer - diag, denom = 1-K
//   out = b_a * S_a + 1  with  b_a = (b1b2 + b1u2 + b2u1)/denom, S_a = C*denom/(u1u2)
// denom cancels exactly; with e = alpha - 1 and b/u = e/C:
//   out = e1*e2/C + e1 + e2 + 1
// Pure elementwise -> layout-independent streaming kernel; no reductions,
// no transposes. Traffic = 528 MB (2 reads + 1 write), the information floor.
//
// FINAL: flat float4 kernel, 256 thr, one float4/thread. Measured twice at
// 71.8-73.0us kernel / 78.3-78.6us harness, 6.72-6.82 TB/s (84-86% of 8TB/s
// HBM spec) = the mixed read:write stream controller ceiling on sm_103a.
// Tested and rejected: deeper per-thread MLP + streaming cache hints (R2,
// neutral), persistent single-wave launch (R3, -5%). All compute pipes <12%.

#define INV_C (1.0f / 21.0f)

__global__ void __launch_bounds__(256)
ds_combine_kernel(const float4* __restrict__ a1,
                  const float4* __restrict__ a2,
                  float4* __restrict__ out,
                  int n4)
{
    int i = blockIdx.x * blockDim.x + threadIdx.x;
    if (i >= n4) return;

    float4 x = a1[i];
    float4 y = a2[i];
    float4 r;

    // out = (x-1)*(y-1)/C + x + y - 1
    float e1, e2;
    e1 = x.x - 1.0f; e2 = y.x - 1.0f; r.x = fmaf(e1 * e2, INV_C, x.x + y.x - 1.0f);
    e1 = x.y - 1.0f; e2 = y.y - 1.0f; r.y = fmaf(e1 * e2, INV_C, x.y + y.y - 1.0f);
    e1 = x.z - 1.0f; e2 = y.z - 1.0f; r.z = fmaf(e1 * e2, INV_C, x.z + y.z - 1.0f);
    e1 = x.w - 1.0f; e2 = y.w - 1.0f; r.w = fmaf(e1 * e2, INV_C, x.w + y.w - 1.0f);

    out[i] = r;
}

extern "C" void kernel_launch(void* const* d_in, const int* in_sizes, int n_in,
                              void* d_out, int out_size)
{
    const float* a1 = (const float*)d_in[0];
    const float* a2 = (const float*)d_in[1];
    float* out = (float*)d_out;

    int n = in_sizes[0];           // 8*21*512*512 = 44,040,192 (multiple of 4)
    int n4 = n >> 2;               // 11,010,048 float4s

    const int threads = 256;
    int blocks = (n4 + threads - 1) / threads;

    ds_combine_kernel<<<blocks, threads>>>(
        (const float4*)a1, (const float4*)a2, (float4*)out, n4);
}